// round 15
// baseline (speedup 1.0000x reference)
#include <cuda_runtime.h>
#include <math.h>

// Problem constants (fixed by the dataset)
#define D      300
#define D4     75      // D / 4 (float4 slabs; 1200B rows are 16B-aligned)
#define NCTX   10
#define NNEG   20
#define NROWS  21      // 1 positive + 20 negatives
#define B_MAX  16384
#define T2     256
#define NWARPS (T2 / 32)

// Scratch: per-batch mean-pooled context embedding (19.66 MB) + double accumulator.
__device__ __align__(16) float g_ctx_mean[(size_t)B_MAX * D];
__device__ double g_acc;

__device__ __forceinline__ float log_sigmoid(float x) {
    // numerically stable: min(x,0) - log1p(exp(-|x|))
    return fminf(x, 0.0f) - log1pf(__expf(-fabsf(x)));
}

__global__ void zero_acc_kernel() { g_acc = 0.0; }

__global__ void finalize_kernel(float* __restrict__ out, float neg_inv_B) {
    out[0] = (float)(g_acc) * neg_inv_B;
}

// ---- Kernel 1: ctx mean. Only in_embed traffic -> in table stays L2-resident. ----
__global__ __launch_bounds__(96)
void ctx_mean_kernel(const int* __restrict__ ctx_words,  // [B, NCTX]
                     const float* __restrict__ in_w)     // [V, D]
{
    const int b   = blockIdx.x;
    const int tid = threadIdx.x;

    __shared__ int s_cidx[NCTX];
    if (tid < NCTX) s_cidx[tid] = ctx_words[b * NCTX + tid];
    __syncthreads();

    if (tid < D4) {
        float4 acc = make_float4(0.f, 0.f, 0.f, 0.f);
        #pragma unroll
        for (int c = 0; c < NCTX; c++) {
            const float4* row = reinterpret_cast<const float4*>(
                in_w + (size_t)s_cidx[c] * D);
            float4 v = __ldg(&row[tid]);
            acc.x += v.x; acc.y += v.y; acc.z += v.z; acc.w += v.w;
        }
        const float inv = 1.0f / (float)NCTX;
        float4* dst = reinterpret_cast<float4*>(g_ctx_mean + (size_t)b * D);
        dst[tid] = make_float4(acc.x * inv, acc.y * inv, acc.z * inv, acc.w * inv);
    }
}

// ---- Kernel 2: 21 dot products + log_sigmoid. Only out_embed competes for L2
//      (ctx-mean reads use evict-first streaming loads). ----
__global__ __launch_bounds__(T2)
void score_kernel(const int* __restrict__ center_word, // [B]
                  const int* __restrict__ neg_words,   // [B, NNEG]
                  const float* __restrict__ out_w)     // [V, D]
{
    const int b    = blockIdx.x;
    const int tid  = threadIdx.x;
    const int warp = tid >> 5;
    const int lane = tid & 31;

    __shared__ __align__(16) float4 s_cm[D4];
    __shared__ float s_warp[NWARPS];
    __shared__ int   s_tidx[NROWS];

    // stage target indices (warp 0) and ctx-mean (warps 2-4, streaming loads)
    if (tid < NROWS)
        s_tidx[tid] = (tid == 0) ? center_word[b]
                                 : neg_words[b * NNEG + (tid - 1)];
    if (tid >= 64 && tid < 64 + D4) {
        int j = tid - 64;
        s_cm[j] = __ldcs(reinterpret_cast<const float4*>(
                             g_ctx_mean + (size_t)b * D) + j);
    }
    __syncthreads();

    float wsum = 0.0f;
    for (int r = warp; r < NROWS; r += NWARPS) {
        const float4* row = reinterpret_cast<const float4*>(
            out_w + (size_t)s_tidx[r] * D);
        float p = 0.0f;
        #pragma unroll
        for (int j = lane; j < D4; j += 32) {
            float4 a = __ldg(&row[j]);
            float4 c = s_cm[j];
            p = fmaf(a.x, c.x, p);
            p = fmaf(a.y, c.y, p);
            p = fmaf(a.z, c.z, p);
            p = fmaf(a.w, c.w, p);
        }
        #pragma unroll
        for (int o = 16; o > 0; o >>= 1)
            p += __shfl_xor_sync(0xffffffffu, p, o);
        if (lane == 0) {
            float score = (r == 0) ? p : -p;   // negatives: log_sigmoid(-score)
            wsum += log_sigmoid(score);
        }
    }
    if (lane == 0) s_warp[warp] = wsum;
    __syncthreads();

    if (tid == 0) {
        float s = 0.0f;
        #pragma unroll
        for (int w = 0; w < NWARPS; w++) s += s_warp[w];
        atomicAdd(&g_acc, (double)s);   // order-independent accumulation
    }
}

extern "C" void kernel_launch(void* const* d_in, const int* in_sizes, int n_in,
                              void* d_out, int out_size) {
    const int*   ctx_words   = (const int*)d_in[0];   // [B, NCTX]
    const int*   center_word = (const int*)d_in[1];   // [B]
    const int*   neg_words   = (const int*)d_in[2];   // [B, NNEG]
    const float* in_w        = (const float*)d_in[3]; // [V, D]
    const float* out_w       = (const float*)d_in[4]; // [V, D]
    float*       out         = (float*)d_out;

    const int B = in_sizes[1];

    zero_acc_kernel<<<1, 1>>>();
    ctx_mean_kernel<<<B, 96>>>(ctx_words, in_w);
    score_kernel<<<B, T2>>>(center_word, neg_words, out_w);
    finalize_kernel<<<1, 1>>>(out, -1.0f / (float)B);
}

// round 16
// speedup vs baseline: 1.0315x; 1.0315x over previous
#include <cuda_runtime.h>
#include <math.h>

// Problem constants (fixed by the dataset)
#define D      300
#define D4     75      // D / 4 (float4 slabs; 1200B rows are 16B-aligned)
#define NCTX   10
#define NNEG   20
#define NROWS  21      // 1 positive + 20 negatives
#define B_MAX  16384
#define T2     224     // 7 warps -> exactly 3 rows per warp
#define NWARPS (T2 / 32)

// Scratch: per-batch mean-pooled context embedding (19.66 MB),
// double accumulator, and a ticket for the last-CTA finalize.
__device__ __align__(16) float g_ctx_mean[(size_t)B_MAX * D];
__device__ double g_acc;
__device__ unsigned int g_ticket;   // zero-init; reset by last CTA each launch

__device__ __forceinline__ float log_sigmoid(float x) {
    // numerically stable: min(x,0) - log1p(exp(-|x|))
    return fminf(x, 0.0f) - log1pf(__expf(-fabsf(x)));
}

// ---- Kernel 1: ctx mean. Only in_embed traffic -> best L2 behavior for it.
//      Block 0 also re-zeroes the accumulator (safe: K2 runs strictly after). ----
__global__ __launch_bounds__(96)
void ctx_mean_kernel(const int* __restrict__ ctx_words,  // [B, NCTX]
                     const float* __restrict__ in_w)     // [V, D]
{
    const int b   = blockIdx.x;
    const int tid = threadIdx.x;

    if (b == 0 && tid == 95) g_acc = 0.0;

    __shared__ int s_cidx[NCTX];
    if (tid < NCTX) s_cidx[tid] = ctx_words[b * NCTX + tid];
    __syncthreads();

    if (tid < D4) {
        float4 acc = make_float4(0.f, 0.f, 0.f, 0.f);
        #pragma unroll
        for (int c = 0; c < NCTX; c++) {
            const float4* row = reinterpret_cast<const float4*>(
                in_w + (size_t)s_cidx[c] * D);
            float4 v = __ldg(&row[tid]);
            acc.x += v.x; acc.y += v.y; acc.z += v.z; acc.w += v.w;
        }
        const float inv = 1.0f / (float)NCTX;
        float4* dst = reinterpret_cast<float4*>(g_ctx_mean + (size_t)b * D);
        dst[tid] = make_float4(acc.x * inv, acc.y * inv, acc.z * inv, acc.w * inv);
    }
}

// ---- Kernel 2: 21 dot products + log_sigmoid, per-CTA double atomic,
//      last CTA finalizes the scalar output (no extra launches). ----
__global__ __launch_bounds__(T2)
void score_kernel(const int* __restrict__ center_word, // [B]
                  const int* __restrict__ neg_words,   // [B, NNEG]
                  const float* __restrict__ out_w,     // [V, D]
                  float* __restrict__ out,             // [1]
                  float neg_inv_B)
{
    const int b    = blockIdx.x;
    const int tid  = threadIdx.x;
    const int warp = tid >> 5;
    const int lane = tid & 31;

    __shared__ __align__(16) float4 s_cm[D4];
    __shared__ float s_warp[NWARPS];
    __shared__ int   s_tidx[NROWS];

    // stage target indices (warp 0) and ctx-mean (streaming, evict-first)
    if (tid < NROWS)
        s_tidx[tid] = (tid == 0) ? center_word[b]
                                 : neg_words[b * NNEG + (tid - 1)];
    if (tid >= 64 && tid < 64 + D4) {
        int j = tid - 64;
        s_cm[j] = __ldcs(reinterpret_cast<const float4*>(
                             g_ctx_mean + (size_t)b * D) + j);
    }
    __syncthreads();

    float wsum = 0.0f;
    #pragma unroll
    for (int rr = 0; rr < 3; rr++) {             // 7 warps x 3 rows = 21 exactly
        const int r = warp + rr * NWARPS;
        const float4* row = reinterpret_cast<const float4*>(
            out_w + (size_t)s_tidx[r] * D);
        float p = 0.0f;
        #pragma unroll
        for (int j = lane; j < D4; j += 32) {
            float4 a = __ldg(&row[j]);
            float4 c = s_cm[j];
            p = fmaf(a.x, c.x, p);
            p = fmaf(a.y, c.y, p);
            p = fmaf(a.z, c.z, p);
            p = fmaf(a.w, c.w, p);
        }
        #pragma unroll
        for (int o = 16; o > 0; o >>= 1)
            p += __shfl_xor_sync(0xffffffffu, p, o);
        if (lane == 0) {
            float score = (r == 0) ? p : -p;     // negatives: log_sigmoid(-score)
            wsum += log_sigmoid(score);
        }
    }
    if (lane == 0) s_warp[warp] = wsum;
    __syncthreads();

    if (tid == 0) {
        float s = 0.0f;
        #pragma unroll
        for (int w = 0; w < NWARPS; w++) s += s_warp[w];
        atomicAdd(&g_acc, (double)s);            // order-independent accumulation
        __threadfence();
        unsigned t = atomicAdd(&g_ticket, 1u);
        if (t == gridDim.x - 1) {                // last CTA: finalize + reset
            g_ticket = 0;                        // deterministic across graph replays
            double total = atomicAdd(&g_acc, 0.0);  // L2-coherent read
            out[0] = (float)total * neg_inv_B;
        }
    }
}

extern "C" void kernel_launch(void* const* d_in, const int* in_sizes, int n_in,
                              void* d_out, int out_size) {
    const int*   ctx_words   = (const int*)d_in[0];   // [B, NCTX]
    const int*   center_word = (const int*)d_in[1];   // [B]
    const int*   neg_words   = (const int*)d_in[2];   // [B, NNEG]
    const float* in_w        = (const float*)d_in[3]; // [V, D]
    const float* out_w       = (const float*)d_in[4]; // [V, D]
    float*       out         = (float*)d_out;

    const int B = in_sizes[1];

    ctx_mean_kernel<<<B, 96>>>(ctx_words, in_w);
    score_kernel<<<B, T2>>>(center_word, neg_words, out_w, out,
                            -1.0f / (float)B);
}